// round 7
// baseline (speedup 1.0000x reference)
#include <cuda_runtime.h>
#include <cuda_bf16.h>
#include <cstdint>

// Problem constants (fixed by the dataset)
#define N_LEFT   100000
#define N_RIGHT  100000
#define N_EDGES  600000
#define EMB      128

// ---------------------------------------------------------------------------
// Device scratch (allocation-free rule: __device__ globals)
// ---------------------------------------------------------------------------
__device__ float g_L [N_LEFT  * EMB];   // transformed left (gather source)
__device__ float g_S [N_RIGHT * EMB];   // transformed right
__device__ float g_Ml[EMB * EMB];       // Wl2 @ Wo1[0:128]
__device__ float g_Mr[EMB * EMB];       // Wr2 @ Wo1[128:256]
__device__ float g_cl[EMB];
__device__ float g_cr[EMB];

// CSR scratch
__device__ int   g_cnt [N_RIGHT];       // counts, then cursors
__device__ int   g_rowptr[N_RIGHT + 1];
__device__ int   g_excl[N_RIGHT];
__device__ int   g_part[1024];
__device__ int   g_partoff[1024];
__device__ int2  g_epack[N_EDGES];      // (src, bitcast(weight))

// Pre-transposed bf16 hi/lo weight images, [n][k] k-contiguous (B^T layout).
__device__ __align__(16) __nv_bfloat16 g_Wl1T[2][EMB * 64];
__device__ __align__(16) __nv_bfloat16 g_Wr1T[2][EMB * 64];
__device__ __align__(16) __nv_bfloat16 g_MlT [2][EMB * EMB];
__device__ __align__(16) __nv_bfloat16 g_MrT [2][EMB * EMB];
__device__ __align__(16) __nv_bfloat16 g_Wo2T[2][EMB * EMB];

// ---------------------------------------------------------------------------
// PTX helpers (all baseline sm_80+)
// ---------------------------------------------------------------------------
__device__ __forceinline__ void mma16816(float* d, const uint32_t* a, const uint32_t* b) {
    asm volatile(
        "mma.sync.aligned.m16n8k16.row.col.f32.bf16.bf16.f32 "
        "{%0,%1,%2,%3}, {%4,%5,%6,%7}, {%8,%9}, {%0,%1,%2,%3};"
        : "+f"(d[0]), "+f"(d[1]), "+f"(d[2]), "+f"(d[3])
        : "r"(a[0]), "r"(a[1]), "r"(a[2]), "r"(a[3]), "r"(b[0]), "r"(b[1]));
}
__device__ __forceinline__ void ldsm_x4(uint32_t& r0, uint32_t& r1, uint32_t& r2, uint32_t& r3,
                                        uint32_t addr) {
    asm volatile("ldmatrix.sync.aligned.m8n8.x4.shared.b16 {%0,%1,%2,%3}, [%4];"
                 : "=r"(r0), "=r"(r1), "=r"(r2), "=r"(r3) : "r"(addr));
}
__device__ __forceinline__ uint32_t cvta_s(const void* p) {
    return (uint32_t)__cvta_generic_to_shared(p);
}
__device__ __forceinline__ void cp_async16(uint32_t dst, const void* src) {
    asm volatile("cp.async.cg.shared.global [%0], [%1], 16;" :: "r"(dst), "l"(src));
}
__device__ __forceinline__ void cp_commit() {
    asm volatile("cp.async.commit_group;");
}
__device__ __forceinline__ void cp_wait0() {
    asm volatile("cp.async.wait_group 0;");
}
// streaming load: keep out of L1 (protects weight images + epack)
__device__ __forceinline__ float4 ldg_na(const float* p) {
    float4 v;
    asm volatile("ld.global.L1::no_allocate.v4.f32 {%0,%1,%2,%3}, [%4];"
                 : "=f"(v.x), "=f"(v.y), "=f"(v.z), "=f"(v.w) : "l"(p));
    return v;
}

// ---------------------------------------------------------------------------
// MMA stage: acc[MT][4][4] += split3( A[MT*32][K] @ B[128][K]^T )
// smem row stride K+8 (16B-aligned rows, conflict-free ldmatrix).
// ---------------------------------------------------------------------------
template<int K, int MT>
__device__ __forceinline__ void mma_stage(const __nv_bfloat16* __restrict__ Ahi,
                                          const __nv_bfloat16* __restrict__ Alo,
                                          const __nv_bfloat16* __restrict__ Bhi,
                                          const __nv_bfloat16* __restrict__ Blo,
                                          float acc[][4][4],
                                          int warp_m, int warp_n, int lane)
{
    constexpr int SK = K + 8;
    const int tr = lane & 7, quad = lane >> 3;
    const int a_row = warp_m * (MT * 16) + tr + (quad & 1) * 8;
    const int a_col = (quad >> 1) * 8;
    const int b_row = warp_n * 32 + tr + (quad >> 1) * 8;
    const int b_col = (quad & 1) * 8;

    uint32_t aAh = cvta_s(Ahi) + (uint32_t)(a_row * SK + a_col) * 2;
    uint32_t aAl = cvta_s(Alo) + (uint32_t)(a_row * SK + a_col) * 2;
    uint32_t aBh = cvta_s(Bhi) + (uint32_t)(b_row * SK + b_col) * 2;
    uint32_t aBl = cvta_s(Blo) + (uint32_t)(b_row * SK + b_col) * 2;

#pragma unroll
    for (int kc = 0; kc < K / 16; kc++) {
        const uint32_t ko = kc * 32;   // 16 elems = 32 bytes
        uint32_t ah[MT][4], al[MT][4], bh[2][4], bl[2][4];
#pragma unroll
        for (int mt = 0; mt < MT; mt++) {
            const uint32_t mo = (uint32_t)(mt * 16 * SK) * 2 + ko;
            ldsm_x4(ah[mt][0], ah[mt][1], ah[mt][2], ah[mt][3], aAh + mo);
            ldsm_x4(al[mt][0], al[mt][1], al[mt][2], al[mt][3], aAl + mo);
        }
#pragma unroll
        for (int np = 0; np < 2; np++) {
            const uint32_t no = (uint32_t)(np * 16 * SK) * 2 + ko;
            ldsm_x4(bh[np][0], bh[np][1], bh[np][2], bh[np][3], aBh + no);
            ldsm_x4(bl[np][0], bl[np][1], bl[np][2], bl[np][3], aBl + no);
        }
#pragma unroll
        for (int mt = 0; mt < MT; mt++)
#pragma unroll
            for (int nt = 0; nt < 4; nt++) {
                const uint32_t* ph = &bh[nt >> 1][(nt & 1) * 2];
                const uint32_t* pl = &bl[nt >> 1][(nt & 1) * 2];
                mma16816(acc[mt][nt], ah[mt], ph);
                mma16816(acc[mt][nt], ah[mt], pl);
                mma16816(acc[mt][nt], al[mt], ph);
            }
    }
}

// Async copy a [128][K] bf16 image from gmem (packed) into padded smem.
template<int K>
__device__ __forceinline__ void load_B_async(__nv_bfloat16* __restrict__ dst,
                                             const uint4* __restrict__ src, int tid)
{
    constexpr int SK = K + 8;
    constexpr int NV = 128 * K / 8;
#pragma unroll
    for (int i = tid; i < NV; i += 256) {
        const int row = i / (K / 8);
        const int col = (i % (K / 8)) * 8;
        cp_async16(cvta_s(dst + row * SK + col), src + i);
    }
}

// Load A[row0..+63][0..K) fp32 from gmem, bf16 hi/lo split, padded smem.
template<int K>
__device__ __forceinline__ void load_A64(__nv_bfloat16* __restrict__ hi,
                                         __nv_bfloat16* __restrict__ lo,
                                         const float* __restrict__ X,
                                         int row0, int M, int tid)
{
    constexpr int SK = K + 8;
    const int row  = tid >> 2;
    const int grow = row0 + row;
    const bool valid = grow < M;
    const float* xr = X + (size_t)grow * K;
    const int cbase = (tid & 3) * (K / 4);
#pragma unroll
    for (int q = 0; q < K / 16; q++) {
        const int c0 = cbase + q * 4;
        float4 v = valid ? *(const float4*)(xr + c0) : make_float4(0.f, 0.f, 0.f, 0.f);
        __nv_bfloat16 hx = __float2bfloat16(v.x), hy = __float2bfloat16(v.y);
        __nv_bfloat16 hz = __float2bfloat16(v.z), hw = __float2bfloat16(v.w);
        __nv_bfloat16 lx = __float2bfloat16(v.x - __bfloat162float(hx));
        __nv_bfloat16 ly = __float2bfloat16(v.y - __bfloat162float(hy));
        __nv_bfloat16 lz = __float2bfloat16(v.z - __bfloat162float(hz));
        __nv_bfloat16 lw = __float2bfloat16(v.w - __bfloat162float(hw));
        __nv_bfloat162 h0(hx, hy), h1(hz, hw), l0(lx, ly), l1(lz, lw);
        *(uint32_t*)(hi + row * SK + c0)     = *(uint32_t*)&h0;
        *(uint32_t*)(hi + row * SK + c0 + 2) = *(uint32_t*)&h1;
        *(uint32_t*)(lo + row * SK + c0)     = *(uint32_t*)&l0;
        *(uint32_t*)(lo + row * SK + c0 + 2) = *(uint32_t*)&l1;
    }
}

// ---------------------------------------------------------------------------
// Fused 2-layer MLP, M=64 per CTA, overlaid smem (2 CTAs/SM):
//   C = relu(X @ W1 [+ b1]) @ W2 + b2
// ---------------------------------------------------------------------------
#define K1 64
#define K2 128
#define SK1 (K1 + 8)
#define SK2 (K2 + 8)
#define M_B1H 0
#define M_B1L (128 * SK1)                   // 9216
#define M_A1H (2 * 128 * SK1)               // 18432
#define M_A1L (M_A1H + 64 * SK1)            // 23040
#define M_HH  0
#define M_HL  (64 * SK2)                    // 8704
#define M_B2H 18432
#define M_B2L (M_B2H + 128 * SK2)           // 35840
#define MLP_SMEM_ELEMS (M_B2L + 128 * SK2)  // 53248
#define MLP_SMEM_BYTES (MLP_SMEM_ELEMS * 2) // 106496

__global__ void __launch_bounds__(256, 2)
mlp_kernel(const float* __restrict__ X,
           const uint4* __restrict__ B1hi, const uint4* __restrict__ B1lo,
           const float* __restrict__ bias1,
           const uint4* __restrict__ B2hi, const uint4* __restrict__ B2lo,
           const float* __restrict__ bias2,
           float* __restrict__ C, int M)
{
    extern __shared__ __nv_bfloat16 sm[];
    const int tid = threadIdx.x;
    const int wid = tid >> 5, lane = tid & 31;
    const int warp_m = wid >> 2, warp_n = wid & 3;
    const int g = lane >> 2, c = lane & 3;
    const int row0 = blockIdx.x * 64;

    load_B_async<K1>(sm + M_B1H, B1hi, tid);
    load_B_async<K1>(sm + M_B1L, B1lo, tid);
    cp_commit();
    load_A64<K1>(sm + M_A1H, sm + M_A1L, X, row0, M, tid);   // overlaps B1 fetch
    cp_wait0();
    __syncthreads();

    float acc[2][4][4];
#pragma unroll
    for (int mt = 0; mt < 2; mt++)
#pragma unroll
        for (int nt = 0; nt < 4; nt++)
#pragma unroll
            for (int j = 0; j < 4; j++) acc[mt][nt][j] = 0.f;

    mma_stage<K1, 2>(sm + M_A1H, sm + M_A1L, sm + M_B1H, sm + M_B1L,
                     acc, warp_m, warp_n, lane);
    __syncthreads();   // all warps done reading A1/B1

    // prefetch B2 over A1/X region (A1 fully consumed), overlapping epilogue-1
    load_B_async<K2>(sm + M_B2H, B2hi, tid);
    load_B_async<K2>(sm + M_B2L, B2lo, tid);
    cp_commit();

    // epilogue 1: H = relu(acc + b1) -> bf16 hi/lo over B1 region
#pragma unroll
    for (int mt = 0; mt < 2; mt++) {
        const int row = warp_m * 32 + mt * 16 + g;
#pragma unroll
        for (int nt = 0; nt < 4; nt++) {
            const int col = warp_n * 32 + nt * 8 + c * 2;
            float v0 = acc[mt][nt][0], v1 = acc[mt][nt][1];
            float v2 = acc[mt][nt][2], v3 = acc[mt][nt][3];
            if (bias1) {
                float2 b = *(const float2*)(bias1 + col);
                v0 += b.x; v1 += b.y; v2 += b.x; v3 += b.y;
            }
            v0 = fmaxf(v0, 0.f); v1 = fmaxf(v1, 0.f);
            v2 = fmaxf(v2, 0.f); v3 = fmaxf(v3, 0.f);
            __nv_bfloat16 h0 = __float2bfloat16(v0), h1 = __float2bfloat16(v1);
            __nv_bfloat16 h2 = __float2bfloat16(v2), h3 = __float2bfloat16(v3);
            __nv_bfloat162 hp0(h0, h1), hp1(h2, h3);
            __nv_bfloat162 lp0(__float2bfloat16(v0 - __bfloat162float(h0)),
                               __float2bfloat16(v1 - __bfloat162float(h1)));
            __nv_bfloat162 lp1(__float2bfloat16(v2 - __bfloat162float(h2)),
                               __float2bfloat16(v3 - __bfloat162float(h3)));
            *(uint32_t*)(sm + M_HH + row * SK2 + col)       = *(uint32_t*)&hp0;
            *(uint32_t*)(sm + M_HH + (row + 8) * SK2 + col) = *(uint32_t*)&hp1;
            *(uint32_t*)(sm + M_HL + row * SK2 + col)       = *(uint32_t*)&lp0;
            *(uint32_t*)(sm + M_HL + (row + 8) * SK2 + col) = *(uint32_t*)&lp1;
        }
    }
    cp_wait0();
    __syncthreads();

#pragma unroll
    for (int mt = 0; mt < 2; mt++)
#pragma unroll
        for (int nt = 0; nt < 4; nt++)
#pragma unroll
            for (int j = 0; j < 4; j++) acc[mt][nt][j] = 0.f;

    mma_stage<K2, 2>(sm + M_HH, sm + M_HL, sm + M_B2H, sm + M_B2L,
                     acc, warp_m, warp_n, lane);

#pragma unroll
    for (int mt = 0; mt < 2; mt++) {
        const int r = row0 + warp_m * 32 + mt * 16 + g;
#pragma unroll
        for (int nt = 0; nt < 4; nt++) {
            const int col = warp_n * 32 + nt * 8 + c * 2;
            float2 b = *(const float2*)(bias2 + col);
            if (r < M) {
                float2 o0 = make_float2(acc[mt][nt][0] + b.x, acc[mt][nt][1] + b.y);
                *(float2*)(C + (size_t)r * EMB + col) = o0;
            }
            if (r + 8 < M) {
                float2 o1 = make_float2(acc[mt][nt][2] + b.x, acc[mt][nt][3] + b.y);
                *(float2*)(C + (size_t)(r + 8) * EMB + col) = o1;
            }
        }
    }
}

// ---------------------------------------------------------------------------
// Fused gather + output GEMM, M=64 per CTA (2 CTAs/SM):
//   conv_r = S[r] + sum_j w_j * L[src_j];  out = relu(conv + bo1) @ Wo2 + bo2
// Gather: each warp processes 8 rows as 4 lockstep PAIRS with predicated
// 4-batches -> 8 independent L-row loads in flight regardless of degree.
// ---------------------------------------------------------------------------
#define F_AH 0
#define F_AL (64 * SK2)                  // 8704
#define F_BH (2 * 64 * SK2)              // 17408
#define F_BL (F_BH + 128 * SK2)          // 34816
#define F_SMEM_ELEMS (F_BL + 128 * SK2)  // 52224
#define F_SMEM_BYTES (F_SMEM_ELEMS * 2)  // 104448

__global__ void __launch_bounds__(256, 2)
out_fused_kernel(const float* __restrict__ S,
                 const int* __restrict__ rowptr,
                 const int2* __restrict__ epack,
                 const float* __restrict__ L,
                 const uint4* __restrict__ Bhi, const uint4* __restrict__ Blo,
                 const float* __restrict__ bo1,
                 const float* __restrict__ bo2,
                 float* __restrict__ C, int M)
{
    extern __shared__ __nv_bfloat16 sm[];
    const int tid = threadIdx.x;
    const int wid = tid >> 5, lane = tid & 31;
    const int warp_m = wid >> 2, warp_n = wid & 3;
    const int g = lane >> 2, c = lane & 3;
    const int row0 = blockIdx.x * 64;

    load_B_async<K2>(sm + F_BH, Bhi, tid);
    load_B_async<K2>(sm + F_BL, Blo, tid);
    cp_commit();   // fetched during the whole gather

    const float4 pb = *(const float4*)(bo1 + lane * 4);

#pragma unroll 1
    for (int i = 0; i < 8; i += 2) {
        const int rl0 = wid * 8 + i;
        const int r0 = row0 + rl0, r1 = r0 + 1;
        float4 a0 = make_float4(0.f, 0.f, 0.f, 0.f);
        float4 a1 = make_float4(0.f, 0.f, 0.f, 0.f);
        int n0 = 0, n1 = 0, b0 = 0, b1 = 0;
        if (r0 < M) {
            a0 = ldg_na(S + (size_t)r0 * EMB + lane * 4);
            b0 = rowptr[r0]; n0 = rowptr[r0 + 1] - b0;
        }
        if (r1 < M) {
            a1 = ldg_na(S + (size_t)r1 * EMB + lane * 4);
            b1 = rowptr[r1]; n1 = rowptr[r1 + 1] - b1;
        }
        const int nmax = max(n0, n1);
#pragma unroll 1
        for (int t = 0; t < nmax; t += 4) {
            int2 p0[4], p1[4];
#pragma unroll
            for (int u = 0; u < 4; u++) {
                p0[u] = (t + u < n0) ? epack[b0 + t + u] : make_int2(0, 0);
                p1[u] = (t + u < n1) ? epack[b1 + t + u] : make_int2(0, 0);
            }
            float4 v0[4], v1[4];
#pragma unroll
            for (int u = 0; u < 4; u++) {
                v0[u] = ldg_na(L + (size_t)p0[u].x * EMB + lane * 4);
                v1[u] = ldg_na(L + (size_t)p1[u].x * EMB + lane * 4);
            }
#pragma unroll
            for (int u = 0; u < 4; u++) {
                const float w0 = __int_as_float(p0[u].y);
                const float w1 = __int_as_float(p1[u].y);
                a0.x += w0 * v0[u].x; a0.y += w0 * v0[u].y;
                a0.z += w0 * v0[u].z; a0.w += w0 * v0[u].w;
                a1.x += w1 * v1[u].x; a1.y += w1 * v1[u].y;
                a1.z += w1 * v1[u].z; a1.w += w1 * v1[u].w;
            }
        }
        // relu(conv + bo1), split, store both rows to smem A image
#pragma unroll
        for (int p = 0; p < 2; p++) {
            float4 acc = p ? a1 : a0;
            const int rv = p ? r1 : r0;
            if (rv < M) {
                acc.x = fmaxf(acc.x + pb.x, 0.f);
                acc.y = fmaxf(acc.y + pb.y, 0.f);
                acc.z = fmaxf(acc.z + pb.z, 0.f);
                acc.w = fmaxf(acc.w + pb.w, 0.f);
            } else {
                acc = make_float4(0.f, 0.f, 0.f, 0.f);
            }
            __nv_bfloat16 hx = __float2bfloat16(acc.x), hy = __float2bfloat16(acc.y);
            __nv_bfloat16 hz = __float2bfloat16(acc.z), hw = __float2bfloat16(acc.w);
            __nv_bfloat162 h0(hx, hy), h1(hz, hw);
            __nv_bfloat162 l0(__float2bfloat16(acc.x - __bfloat162float(hx)),
                              __float2bfloat16(acc.y - __bfloat162float(hy)));
            __nv_bfloat162 l1(__float2bfloat16(acc.z - __bfloat162float(hz)),
                              __float2bfloat16(acc.w - __bfloat162float(hw)));
            const int rl = rl0 + p;
            const int c0 = lane * 4;
            *(uint32_t*)(sm + F_AH + rl * SK2 + c0)     = *(uint32_t*)&h0;
            *(uint32_t*)(sm + F_AH + rl * SK2 + c0 + 2) = *(uint32_t*)&h1;
            *(uint32_t*)(sm + F_AL + rl * SK2 + c0)     = *(uint32_t*)&l0;
            *(uint32_t*)(sm + F_AL + rl * SK2 + c0 + 2) = *(uint32_t*)&l1;
        }
    }
    cp_wait0();
    __syncthreads();

    float acc[2][4][4];
#pragma unroll
    for (int mt = 0; mt < 2; mt++)
#pragma unroll
        for (int nt = 0; nt < 4; nt++)
#pragma unroll
            for (int j = 0; j < 4; j++) acc[mt][nt][j] = 0.f;

    mma_stage<K2, 2>(sm + F_AH, sm + F_AL, sm + F_BH, sm + F_BL,
                     acc, warp_m, warp_n, lane);

#pragma unroll
    for (int mt = 0; mt < 2; mt++) {
        const int r = row0 + warp_m * 32 + mt * 16 + g;
#pragma unroll
        for (int nt = 0; nt < 4; nt++) {
            const int col = warp_n * 32 + nt * 8 + c * 2;
            float2 b = *(const float2*)(bo2 + col);
            if (r < M) {
                float2 o0 = make_float2(acc[mt][nt][0] + b.x, acc[mt][nt][1] + b.y);
                *(float2*)(C + (size_t)r * EMB + col) = o0;
            }
            if (r + 8 < M) {
                float2 o1 = make_float2(acc[mt][nt][2] + b.x, acc[mt][nt][3] + b.y);
                *(float2*)(C + (size_t)(r + 8) * EMB + col) = o1;
            }
        }
    }
}

// ---------------------------------------------------------------------------
// Weight fusion (matrix rows 0..127, bias row 128) + prep
// ---------------------------------------------------------------------------
__global__ void fuse_wb_kernel(const float* __restrict__ Wl2,
                               const float* __restrict__ Wr2,
                               const float* __restrict__ bl2,
                               const float* __restrict__ br2,
                               const float* __restrict__ Wo1,
                               float* __restrict__ Ml, float* __restrict__ Mr,
                               float* __restrict__ cl, float* __restrict__ cr)
{
    const int i = blockIdx.x, j = threadIdx.x;
    const bool rs = (blockIdx.y != 0);
    const int off = rs ? EMB : 0;
    const float* vec = (i < EMB) ? ((rs ? Wr2 : Wl2) + i * EMB) : (rs ? br2 : bl2);
    float s = 0.f;
#pragma unroll 8
    for (int k = 0; k < EMB; k++)
        s += vec[k] * Wo1[(off + k) * EMB + j];
    if (i < EMB) (rs ? Mr : Ml)[i * EMB + j] = s;
    else         (rs ? cr : cl)[j] = s;
}

__global__ void prep_weights_kernel(const float* __restrict__ Wl1,
                                    const float* __restrict__ Wr1,
                                    const float* __restrict__ Ml,
                                    const float* __restrict__ Mr,
                                    const float* __restrict__ Wo2,
                                    __nv_bfloat16* __restrict__ Wl1T,
                                    __nv_bfloat16* __restrict__ Wr1T,
                                    __nv_bfloat16* __restrict__ MlT,
                                    __nv_bfloat16* __restrict__ MrT,
                                    __nv_bfloat16* __restrict__ Wo2T)
{
    const int n = threadIdx.x;
    const float* W; __nv_bfloat16* T; int K;
    switch (blockIdx.x) {
        case 0: W = Wl1; T = Wl1T; K = 64;  break;
        case 1: W = Wr1; T = Wr1T; K = 64;  break;
        case 2: W = Ml;  T = MlT;  K = 128; break;
        case 3: W = Mr;  T = MrT;  K = 128; break;
        default: W = Wo2; T = Wo2T; K = 128; break;
    }
    __nv_bfloat16* Hi = T;
    __nv_bfloat16* Lo = T + EMB * K;
    for (int k = 0; k < K; k++) {
        float w = W[k * EMB + n];
        __nv_bfloat16 h = __float2bfloat16(w);
        __nv_bfloat16 l = __float2bfloat16(w - __bfloat162float(h));
        Hi[n * K + k] = h;
        Lo[n * K + k] = l;
    }
}

// ---------------------------------------------------------------------------
// CSR build: histogram -> block-scan -> offsets -> fill (packed payload)
// ---------------------------------------------------------------------------
__global__ void hist_kernel(const int* __restrict__ eidx, int* __restrict__ cnt, int E) {
    const int e = blockIdx.x * blockDim.x + threadIdx.x;
    if (e < E) atomicAdd(&cnt[eidx[E + e]], 1);
}

__global__ void scan_block_kernel(const int* __restrict__ cnt, int* __restrict__ excl,
                                  int* __restrict__ part, int n) {
    __shared__ int sh[512];
    const int tid = threadIdx.x;
    const int i = blockIdx.x * 512 + tid;
    int v = (i < n) ? cnt[i] : 0;
    int x = v;
    sh[tid] = x;
    __syncthreads();
#pragma unroll
    for (int d = 1; d < 512; d <<= 1) {
        int t = (tid >= d) ? sh[tid - d] : 0;
        __syncthreads();
        x += t;
        sh[tid] = x;
        __syncthreads();
    }
    if (i < n) excl[i] = x - v;
    if (tid == 511) part[blockIdx.x] = x;
}

__global__ void scan_part_kernel(int* __restrict__ part, int* __restrict__ partoff, int nb) {
    __shared__ int sh[1024];
    const int tid = threadIdx.x;
    int v = (tid < nb) ? part[tid] : 0;
    int x = v;
    sh[tid] = x;
    __syncthreads();
#pragma unroll
    for (int d = 1; d < 1024; d <<= 1) {
        int t = (tid >= d) ? sh[tid - d] : 0;
        __syncthreads();
        x += t;
        sh[tid] = x;
        __syncthreads();
    }
    if (tid < nb) partoff[tid] = x - v;
}

__global__ void finalize_rowptr_kernel(const int* __restrict__ excl,
                                       const int* __restrict__ partoff,
                                       int* __restrict__ rowptr,
                                       int* __restrict__ cursor,
                                       int n, int E) {
    const int i = blockIdx.x * 512 + threadIdx.x;
    if (i < n) {
        int r = excl[i] + partoff[blockIdx.x];
        rowptr[i] = r;
        cursor[i] = r;
    }
    if (i == 0) rowptr[n] = E;
}

__global__ void fill_kernel(const int* __restrict__ eidx, const float* __restrict__ ew,
                            int* __restrict__ cursor,
                            int2* __restrict__ epack, int E) {
    const int e = blockIdx.x * blockDim.x + threadIdx.x;
    if (e >= E) return;
    const int src = eidx[e];
    const int dst = eidx[E + e];
    const int pos = atomicAdd(&cursor[dst], 1);
    epack[pos] = make_int2(src, __float_as_int(ew[e]));
}

// ---------------------------------------------------------------------------
// Launch
// ---------------------------------------------------------------------------
extern "C" void kernel_launch(void* const* d_in, const int* in_sizes, int n_in,
                              void* d_out, int out_size)
{
    const float* left  = (const float*)d_in[0];
    const int*   eidx  = (const int*)  d_in[1];
    const float* ew    = (const float*)d_in[2];
    const float* right = (const float*)d_in[3];
    const float* Wl1 = (const float*)d_in[5];
    const float* bl1 = (const float*)d_in[6];
    const float* Wl2 = (const float*)d_in[7];
    const float* bl2 = (const float*)d_in[8];
    const float* Wr1 = (const float*)d_in[9];
    const float* Wr2 = (const float*)d_in[10];
    const float* br2 = (const float*)d_in[11];
    const float* Wo1 = (const float*)d_in[12];
    const float* bo1 = (const float*)d_in[13];
    const float* Wo2 = (const float*)d_in[14];
    const float* bo2 = (const float*)d_in[15];

    const int nL = in_sizes[0] / 64;
    const int E  = in_sizes[1] / 2;
    const int nR = in_sizes[3] / 64;
    const int nO = out_size / EMB;

    float *gL, *gS, *gMl, *gMr, *gcl, *gcr;
    cudaGetSymbolAddress((void**)&gL,  g_L);
    cudaGetSymbolAddress((void**)&gS,  g_S);
    cudaGetSymbolAddress((void**)&gMl, g_Ml);
    cudaGetSymbolAddress((void**)&gMr, g_Mr);
    cudaGetSymbolAddress((void**)&gcl, g_cl);
    cudaGetSymbolAddress((void**)&gcr, g_cr);

    int *gCnt, *gRow, *gExcl, *gPart, *gPoff;
    int2* gEpack;
    cudaGetSymbolAddress((void**)&gCnt,   g_cnt);
    cudaGetSymbolAddress((void**)&gRow,   g_rowptr);
    cudaGetSymbolAddress((void**)&gExcl,  g_excl);
    cudaGetSymbolAddress((void**)&gPart,  g_part);
    cudaGetSymbolAddress((void**)&gPoff,  g_partoff);
    cudaGetSymbolAddress((void**)&gEpack, g_epack);

    __nv_bfloat16 *wl1t, *wr1t, *mlt, *mrt, *wo2t;
    cudaGetSymbolAddress((void**)&wl1t, g_Wl1T);
    cudaGetSymbolAddress((void**)&wr1t, g_Wr1T);
    cudaGetSymbolAddress((void**)&mlt,  g_MlT);
    cudaGetSymbolAddress((void**)&mrt,  g_MrT);
    cudaGetSymbolAddress((void**)&wo2t, g_Wo2T);

    cudaFuncSetAttribute(mlp_kernel,       cudaFuncAttributeMaxDynamicSharedMemorySize, MLP_SMEM_BYTES);
    cudaFuncSetAttribute(out_fused_kernel, cudaFuncAttributeMaxDynamicSharedMemorySize, F_SMEM_BYTES);

    const int gridL = (nL + 63) / 64;
    const int gridR = (nR + 63) / 64;
    const int gridO = (nO + 63) / 64;
    const int NB = (nR + 511) / 512;

    const uint4* wl1h = (const uint4*)wl1t;
    const uint4* wl1l = (const uint4*)(wl1t + EMB * 64);
    const uint4* wr1h = (const uint4*)wr1t;
    const uint4* wr1l = (const uint4*)(wr1t + EMB * 64);
    const uint4* mlh  = (const uint4*)mlt;
    const uint4* mll  = (const uint4*)(mlt + EMB * EMB);
    const uint4* mrh  = (const uint4*)mrt;
    const uint4* mrl  = (const uint4*)(mrt + EMB * EMB);
    const uint4* wo2h = (const uint4*)wo2t;
    const uint4* wo2l = (const uint4*)(wo2t + EMB * EMB);

    // launch index 0
    fuse_wb_kernel<<<dim3(EMB + 1, 2), EMB>>>(Wl2, Wr2, bl2, br2, Wo1, gMl, gMr, gcl, gcr);
    // launch index 1
    prep_weights_kernel<<<5, EMB>>>(Wl1, Wr1, gMl, gMr, Wo2, wl1t, wr1t, mlt, mrt, wo2t);
    // (memset — not counted by the profiler's launch index)
    cudaMemsetAsync(gCnt, 0, (size_t)nR * sizeof(int));
    // launch index 2
    hist_kernel<<<(E + 255) / 256, 256>>>(eidx, gCnt, E);
    // launch index 3  <- profiler capture target
    mlp_kernel<<<gridL, 256, MLP_SMEM_BYTES>>>(left, wl1h, wl1l, bl1, mlh, mll, gcl, gL, nL);
    // launch index 4
    mlp_kernel<<<gridR, 256, MLP_SMEM_BYTES>>>(right, wr1h, wr1l, nullptr, mrh, mrl, gcr, gS, nR);
    // CSR scan chain
    scan_block_kernel<<<NB, 512>>>(gCnt, gExcl, gPart, nR);
    scan_part_kernel<<<1, 1024>>>(gPart, gPoff, NB);
    finalize_rowptr_kernel<<<NB, 512>>>(gExcl, gPoff, gRow, gCnt, nR, E);
    fill_kernel<<<(E + 255) / 256, 256>>>(eidx, ew, gCnt, gEpack, E);
    // fused gather + output GEMM
    out_fused_kernel<<<gridO, 256, F_SMEM_BYTES>>>(gS, gRow, gEpack, gL,
                                                   wo2h, wo2l, bo1, bo2, (float*)d_out, nO);
}

// round 8
// speedup vs baseline: 1.1007x; 1.1007x over previous
#include <cuda_runtime.h>
#include <cuda_bf16.h>
#include <cstdint>

// Problem constants (fixed by the dataset)
#define N_LEFT   100000
#define N_RIGHT  100000
#define N_EDGES  600000
#define EMB      128

// ---------------------------------------------------------------------------
// Device scratch (allocation-free rule: __device__ globals)
// ---------------------------------------------------------------------------
__device__ float g_L [N_LEFT  * EMB];   // transformed left (gather source)
__device__ float g_S [N_RIGHT * EMB];   // transformed right
__device__ float g_Ml[EMB * EMB];       // Wl2 @ Wo1[0:128]
__device__ float g_Mr[EMB * EMB];       // Wr2 @ Wo1[128:256]
__device__ float g_cl[EMB];
__device__ float g_cr[EMB];

// CSR scratch
__device__ int   g_cnt [N_RIGHT];       // counts, then cursors
__device__ int   g_rowptr[N_RIGHT + 1];
__device__ int   g_excl[N_RIGHT];
__device__ int   g_part[1024];
__device__ int   g_partoff[1024];
__device__ int2  g_epack[N_EDGES];      // (src, bitcast(weight))

// Pre-transposed bf16 hi/lo weight images, [n][k] k-contiguous (B^T layout).
__device__ __align__(16) __nv_bfloat16 g_Wl1T[2][EMB * 64];
__device__ __align__(16) __nv_bfloat16 g_Wr1T[2][EMB * 64];
__device__ __align__(16) __nv_bfloat16 g_MlT [2][EMB * EMB];
__device__ __align__(16) __nv_bfloat16 g_MrT [2][EMB * EMB];
__device__ __align__(16) __nv_bfloat16 g_Wo2T[2][EMB * EMB];

// ---------------------------------------------------------------------------
// PTX helpers (all baseline sm_80+)
// ---------------------------------------------------------------------------
__device__ __forceinline__ void mma16816(float* d, const uint32_t* a, const uint32_t* b) {
    asm volatile(
        "mma.sync.aligned.m16n8k16.row.col.f32.bf16.bf16.f32 "
        "{%0,%1,%2,%3}, {%4,%5,%6,%7}, {%8,%9}, {%0,%1,%2,%3};"
        : "+f"(d[0]), "+f"(d[1]), "+f"(d[2]), "+f"(d[3])
        : "r"(a[0]), "r"(a[1]), "r"(a[2]), "r"(a[3]), "r"(b[0]), "r"(b[1]));
}
__device__ __forceinline__ void ldsm_x4(uint32_t& r0, uint32_t& r1, uint32_t& r2, uint32_t& r3,
                                        uint32_t addr) {
    asm volatile("ldmatrix.sync.aligned.m8n8.x4.shared.b16 {%0,%1,%2,%3}, [%4];"
                 : "=r"(r0), "=r"(r1), "=r"(r2), "=r"(r3) : "r"(addr));
}
__device__ __forceinline__ uint32_t cvta_s(const void* p) {
    return (uint32_t)__cvta_generic_to_shared(p);
}
__device__ __forceinline__ void cp_async16(uint32_t dst, const void* src) {
    asm volatile("cp.async.cg.shared.global [%0], [%1], 16;" :: "r"(dst), "l"(src));
}
__device__ __forceinline__ void cp_commit() {
    asm volatile("cp.async.commit_group;");
}
__device__ __forceinline__ void cp_wait0() {
    asm volatile("cp.async.wait_group 0;");
}

// ---------------------------------------------------------------------------
// MMA stage: acc[MT][4][4] += split3( A[MT*32][K] @ B[128][K]^T )
// smem row stride K+8 (16B-aligned rows, conflict-free ldmatrix).
// ---------------------------------------------------------------------------
template<int K, int MT>
__device__ __forceinline__ void mma_stage(const __nv_bfloat16* __restrict__ Ahi,
                                          const __nv_bfloat16* __restrict__ Alo,
                                          const __nv_bfloat16* __restrict__ Bhi,
                                          const __nv_bfloat16* __restrict__ Blo,
                                          float acc[][4][4],
                                          int warp_m, int warp_n, int lane)
{
    constexpr int SK = K + 8;
    const int tr = lane & 7, quad = lane >> 3;
    const int a_row = warp_m * (MT * 16) + tr + (quad & 1) * 8;
    const int a_col = (quad >> 1) * 8;
    const int b_row = warp_n * 32 + tr + (quad >> 1) * 8;
    const int b_col = (quad & 1) * 8;

    uint32_t aAh = cvta_s(Ahi) + (uint32_t)(a_row * SK + a_col) * 2;
    uint32_t aAl = cvta_s(Alo) + (uint32_t)(a_row * SK + a_col) * 2;
    uint32_t aBh = cvta_s(Bhi) + (uint32_t)(b_row * SK + b_col) * 2;
    uint32_t aBl = cvta_s(Blo) + (uint32_t)(b_row * SK + b_col) * 2;

#pragma unroll
    for (int kc = 0; kc < K / 16; kc++) {
        const uint32_t ko = kc * 32;   // 16 elems = 32 bytes
        uint32_t ah[MT][4], al[MT][4], bh[2][4], bl[2][4];
#pragma unroll
        for (int mt = 0; mt < MT; mt++) {
            const uint32_t mo = (uint32_t)(mt * 16 * SK) * 2 + ko;
            ldsm_x4(ah[mt][0], ah[mt][1], ah[mt][2], ah[mt][3], aAh + mo);
            ldsm_x4(al[mt][0], al[mt][1], al[mt][2], al[mt][3], aAl + mo);
        }
#pragma unroll
        for (int np = 0; np < 2; np++) {
            const uint32_t no = (uint32_t)(np * 16 * SK) * 2 + ko;
            ldsm_x4(bh[np][0], bh[np][1], bh[np][2], bh[np][3], aBh + no);
            ldsm_x4(bl[np][0], bl[np][1], bl[np][2], bl[np][3], aBl + no);
        }
#pragma unroll
        for (int mt = 0; mt < MT; mt++)
#pragma unroll
            for (int nt = 0; nt < 4; nt++) {
                const uint32_t* ph = &bh[nt >> 1][(nt & 1) * 2];
                const uint32_t* pl = &bl[nt >> 1][(nt & 1) * 2];
                mma16816(acc[mt][nt], ah[mt], ph);
                mma16816(acc[mt][nt], ah[mt], pl);
                mma16816(acc[mt][nt], al[mt], ph);
            }
    }
}

// Async copy a [128][K] bf16 image from gmem (packed) into padded smem.
template<int K>
__device__ __forceinline__ void load_B_async(__nv_bfloat16* __restrict__ dst,
                                             const uint4* __restrict__ src, int tid)
{
    constexpr int SK = K + 8;
    constexpr int NV = 128 * K / 8;
#pragma unroll
    for (int i = tid; i < NV; i += 256) {
        const int row = i / (K / 8);
        const int col = (i % (K / 8)) * 8;
        cp_async16(cvta_s(dst + row * SK + col), src + i);
    }
}

// Load A[row0..+63][0..K) fp32 from gmem, bf16 hi/lo split, padded smem.
template<int K>
__device__ __forceinline__ void load_A64(__nv_bfloat16* __restrict__ hi,
                                         __nv_bfloat16* __restrict__ lo,
                                         const float* __restrict__ X,
                                         int row0, int M, int tid)
{
    constexpr int SK = K + 8;
    const int row  = tid >> 2;
    const int grow = row0 + row;
    const bool valid = grow < M;
    const float* xr = X + (size_t)grow * K;
    const int cbase = (tid & 3) * (K / 4);
#pragma unroll
    for (int q = 0; q < K / 16; q++) {
        const int c0 = cbase + q * 4;
        float4 v = valid ? *(const float4*)(xr + c0) : make_float4(0.f, 0.f, 0.f, 0.f);
        __nv_bfloat16 hx = __float2bfloat16(v.x), hy = __float2bfloat16(v.y);
        __nv_bfloat16 hz = __float2bfloat16(v.z), hw = __float2bfloat16(v.w);
        __nv_bfloat16 lx = __float2bfloat16(v.x - __bfloat162float(hx));
        __nv_bfloat16 ly = __float2bfloat16(v.y - __bfloat162float(hy));
        __nv_bfloat16 lz = __float2bfloat16(v.z - __bfloat162float(hz));
        __nv_bfloat16 lw = __float2bfloat16(v.w - __bfloat162float(hw));
        __nv_bfloat162 h0(hx, hy), h1(hz, hw), l0(lx, ly), l1(lz, lw);
        *(uint32_t*)(hi + row * SK + c0)     = *(uint32_t*)&h0;
        *(uint32_t*)(hi + row * SK + c0 + 2) = *(uint32_t*)&h1;
        *(uint32_t*)(lo + row * SK + c0)     = *(uint32_t*)&l0;
        *(uint32_t*)(lo + row * SK + c0 + 2) = *(uint32_t*)&l1;
    }
}

// ---------------------------------------------------------------------------
// MERGED fused 2-layer MLP (left + right in one launch), M=64 per CTA,
// overlaid smem (2 CTAs/SM):  C = relu(X @ W1 [+ b1]) @ W2 + b2
// blockIdx.x < gridL -> left side; else right side.
// ---------------------------------------------------------------------------
#define K1 64
#define K2 128
#define SK1 (K1 + 8)
#define SK2 (K2 + 8)
#define M_B1H 0
#define M_B1L (128 * SK1)                   // 9216
#define M_A1H (2 * 128 * SK1)               // 18432
#define M_A1L (M_A1H + 64 * SK1)            // 23040
#define M_HH  0
#define M_HL  (64 * SK2)                    // 8704
#define M_B2H 18432
#define M_B2L (M_B2H + 128 * SK2)           // 35840
#define MLP_SMEM_ELEMS (M_B2L + 128 * SK2)  // 53248
#define MLP_SMEM_BYTES (MLP_SMEM_ELEMS * 2) // 106496

__global__ void __launch_bounds__(256, 2)
mlp2_kernel(const float* __restrict__ XL, const float* __restrict__ XR,
            const uint4* __restrict__ L_B1hi, const uint4* __restrict__ L_B1lo,
            const uint4* __restrict__ R_B1hi, const uint4* __restrict__ R_B1lo,
            const float* __restrict__ bl1,          // left stage-1 bias (right has none)
            const uint4* __restrict__ L_B2hi, const uint4* __restrict__ L_B2lo,
            const uint4* __restrict__ R_B2hi, const uint4* __restrict__ R_B2lo,
            const float* __restrict__ cl, const float* __restrict__ cr,
            float* __restrict__ CL, float* __restrict__ CR,
            int nL, int nR, int gridL)
{
    extern __shared__ __nv_bfloat16 sm[];
    const int tid = threadIdx.x;
    const int wid = tid >> 5, lane = tid & 31;
    const int warp_m = wid >> 2, warp_n = wid & 3;
    const int g = lane >> 2, c = lane & 3;

    const bool leftSide = (blockIdx.x < gridL);
    const int  bidx  = leftSide ? blockIdx.x : blockIdx.x - gridL;
    const int  row0  = bidx * 64;
    const int  M     = leftSide ? nL : nR;
    const float* X   = leftSide ? XL : XR;
    const uint4* B1hi = leftSide ? L_B1hi : R_B1hi;
    const uint4* B1lo = leftSide ? L_B1lo : R_B1lo;
    const uint4* B2hi = leftSide ? L_B2hi : R_B2hi;
    const uint4* B2lo = leftSide ? L_B2lo : R_B2lo;
    const float* bias1 = leftSide ? bl1 : nullptr;
    const float* bias2 = leftSide ? cl : cr;
    float* C          = leftSide ? CL : CR;

    load_B_async<K1>(sm + M_B1H, B1hi, tid);
    load_B_async<K1>(sm + M_B1L, B1lo, tid);
    cp_commit();
    load_A64<K1>(sm + M_A1H, sm + M_A1L, X, row0, M, tid);   // overlaps B1 fetch
    cp_wait0();
    __syncthreads();

    float acc[2][4][4];
#pragma unroll
    for (int mt = 0; mt < 2; mt++)
#pragma unroll
        for (int nt = 0; nt < 4; nt++)
#pragma unroll
            for (int j = 0; j < 4; j++) acc[mt][nt][j] = 0.f;

    mma_stage<K1, 2>(sm + M_A1H, sm + M_A1L, sm + M_B1H, sm + M_B1L,
                     acc, warp_m, warp_n, lane);
    __syncthreads();   // all warps done reading A1/B1

    // prefetch B2 over A1/X region (A1 fully consumed), overlapping epilogue-1
    load_B_async<K2>(sm + M_B2H, B2hi, tid);
    load_B_async<K2>(sm + M_B2L, B2lo, tid);
    cp_commit();

    // epilogue 1: H = relu(acc + b1) -> bf16 hi/lo over B1 region
#pragma unroll
    for (int mt = 0; mt < 2; mt++) {
        const int row = warp_m * 32 + mt * 16 + g;
#pragma unroll
        for (int nt = 0; nt < 4; nt++) {
            const int col = warp_n * 32 + nt * 8 + c * 2;
            float v0 = acc[mt][nt][0], v1 = acc[mt][nt][1];
            float v2 = acc[mt][nt][2], v3 = acc[mt][nt][3];
            if (bias1) {
                float2 b = *(const float2*)(bias1 + col);
                v0 += b.x; v1 += b.y; v2 += b.x; v3 += b.y;
            }
            v0 = fmaxf(v0, 0.f); v1 = fmaxf(v1, 0.f);
            v2 = fmaxf(v2, 0.f); v3 = fmaxf(v3, 0.f);
            __nv_bfloat16 h0 = __float2bfloat16(v0), h1 = __float2bfloat16(v1);
            __nv_bfloat16 h2 = __float2bfloat16(v2), h3 = __float2bfloat16(v3);
            __nv_bfloat162 hp0(h0, h1), hp1(h2, h3);
            __nv_bfloat162 lp0(__float2bfloat16(v0 - __bfloat162float(h0)),
                               __float2bfloat16(v1 - __bfloat162float(h1)));
            __nv_bfloat162 lp1(__float2bfloat16(v2 - __bfloat162float(h2)),
                               __float2bfloat16(v3 - __bfloat162float(h3)));
            *(uint32_t*)(sm + M_HH + row * SK2 + col)       = *(uint32_t*)&hp0;
            *(uint32_t*)(sm + M_HH + (row + 8) * SK2 + col) = *(uint32_t*)&hp1;
            *(uint32_t*)(sm + M_HL + row * SK2 + col)       = *(uint32_t*)&lp0;
            *(uint32_t*)(sm + M_HL + (row + 8) * SK2 + col) = *(uint32_t*)&lp1;
        }
    }
    cp_wait0();
    __syncthreads();

#pragma unroll
    for (int mt = 0; mt < 2; mt++)
#pragma unroll
        for (int nt = 0; nt < 4; nt++)
#pragma unroll
            for (int j = 0; j < 4; j++) acc[mt][nt][j] = 0.f;

    mma_stage<K2, 2>(sm + M_HH, sm + M_HL, sm + M_B2H, sm + M_B2L,
                     acc, warp_m, warp_n, lane);

#pragma unroll
    for (int mt = 0; mt < 2; mt++) {
        const int r = row0 + warp_m * 32 + mt * 16 + g;
#pragma unroll
        for (int nt = 0; nt < 4; nt++) {
            const int col = warp_n * 32 + nt * 8 + c * 2;
            float2 b = *(const float2*)(bias2 + col);
            if (r < M) {
                float2 o0 = make_float2(acc[mt][nt][0] + b.x, acc[mt][nt][1] + b.y);
                *(float2*)(C + (size_t)r * EMB + col) = o0;
            }
            if (r + 8 < M) {
                float2 o1 = make_float2(acc[mt][nt][2] + b.x, acc[mt][nt][3] + b.y);
                *(float2*)(C + (size_t)(r + 8) * EMB + col) = o1;
            }
        }
    }
}

// ---------------------------------------------------------------------------
// Fused gather + output GEMM, M=64 per CTA (2 CTAs/SM):
//   conv_r = S[r] + sum_j w_j * L[src_j];  out = relu(conv + bo1) @ Wo2 + bo2
// Gather: R6-style simple per-row loop (cached loads), B prefetch via cp.async.
// ---------------------------------------------------------------------------
#define F_AH 0
#define F_AL (64 * SK2)                  // 8704
#define F_BH (2 * 64 * SK2)              // 17408
#define F_BL (F_BH + 128 * SK2)          // 34816
#define F_SMEM_ELEMS (F_BL + 128 * SK2)  // 52224
#define F_SMEM_BYTES (F_SMEM_ELEMS * 2)  // 104448

__global__ void __launch_bounds__(256, 2)
out_fused_kernel(const float* __restrict__ S,
                 const int* __restrict__ rowptr,
                 const int2* __restrict__ epack,
                 const float* __restrict__ L,
                 const uint4* __restrict__ Bhi, const uint4* __restrict__ Blo,
                 const float* __restrict__ bo1,
                 const float* __restrict__ bo2,
                 float* __restrict__ C, int M)
{
    extern __shared__ __nv_bfloat16 sm[];
    const int tid = threadIdx.x;
    const int wid = tid >> 5, lane = tid & 31;
    const int warp_m = wid >> 2, warp_n = wid & 3;
    const int g = lane >> 2, c = lane & 3;
    const int row0 = blockIdx.x * 64;

    load_B_async<K2>(sm + F_BH, Bhi, tid);
    load_B_async<K2>(sm + F_BL, Blo, tid);
    cp_commit();   // fetched during the whole gather

    const float4 pb = *(const float4*)(bo1 + lane * 4);

    // gather: each warp handles 8 rows
#pragma unroll 1
    for (int rl = wid * 8; rl < wid * 8 + 8; rl++) {
        const int r = row0 + rl;
        float4 acc = make_float4(0.f, 0.f, 0.f, 0.f);
        if (r < M) {
            acc = *(const float4*)(S + (size_t)r * EMB + lane * 4);
            const int beg = rowptr[r], end = rowptr[r + 1];
            int j = beg;
            for (; j + 4 <= end; j += 4) {
                const int2 e0 = epack[j],     e1 = epack[j + 1];
                const int2 e2 = epack[j + 2], e3 = epack[j + 3];
                const float4 v0 = *(const float4*)(L + (size_t)e0.x * EMB + lane * 4);
                const float4 v1 = *(const float4*)(L + (size_t)e1.x * EMB + lane * 4);
                const float4 v2 = *(const float4*)(L + (size_t)e2.x * EMB + lane * 4);
                const float4 v3 = *(const float4*)(L + (size_t)e3.x * EMB + lane * 4);
                const float w0 = __int_as_float(e0.y), w1 = __int_as_float(e1.y);
                const float w2 = __int_as_float(e2.y), w3 = __int_as_float(e3.y);
                acc.x += w0 * v0.x + w1 * v1.x + w2 * v2.x + w3 * v3.x;
                acc.y += w0 * v0.y + w1 * v1.y + w2 * v2.y + w3 * v3.y;
                acc.z += w0 * v0.z + w1 * v1.z + w2 * v2.z + w3 * v3.z;
                acc.w += w0 * v0.w + w1 * v1.w + w2 * v2.w + w3 * v3.w;
            }
            for (; j < end; j++) {
                const int2 e0 = epack[j];
                const float w0 = __int_as_float(e0.y);
                const float4 v0 = *(const float4*)(L + (size_t)e0.x * EMB + lane * 4);
                acc.x += w0 * v0.x; acc.y += w0 * v0.y;
                acc.z += w0 * v0.z; acc.w += w0 * v0.w;
            }
            acc.x = fmaxf(acc.x + pb.x, 0.f);
            acc.y = fmaxf(acc.y + pb.y, 0.f);
            acc.z = fmaxf(acc.z + pb.z, 0.f);
            acc.w = fmaxf(acc.w + pb.w, 0.f);
        }
        // split + store into smem A image: row rl, cols lane*4..lane*4+3
        __nv_bfloat16 hx = __float2bfloat16(acc.x), hy = __float2bfloat16(acc.y);
        __nv_bfloat16 hz = __float2bfloat16(acc.z), hw = __float2bfloat16(acc.w);
        __nv_bfloat162 h0(hx, hy), h1(hz, hw);
        __nv_bfloat162 l0(__float2bfloat16(acc.x - __bfloat162float(hx)),
                          __float2bfloat16(acc.y - __bfloat162float(hy)));
        __nv_bfloat162 l1(__float2bfloat16(acc.z - __bfloat162float(hz)),
                          __float2bfloat16(acc.w - __bfloat162float(hw)));
        const int c0 = lane * 4;
        *(uint32_t*)(sm + F_AH + rl * SK2 + c0)     = *(uint32_t*)&h0;
        *(uint32_t*)(sm + F_AH + rl * SK2 + c0 + 2) = *(uint32_t*)&h1;
        *(uint32_t*)(sm + F_AL + rl * SK2 + c0)     = *(uint32_t*)&l0;
        *(uint32_t*)(sm + F_AL + rl * SK2 + c0 + 2) = *(uint32_t*)&l1;
    }
    cp_wait0();
    __syncthreads();

    float acc[2][4][4];
#pragma unroll
    for (int mt = 0; mt < 2; mt++)
#pragma unroll
        for (int nt = 0; nt < 4; nt++)
#pragma unroll
            for (int j = 0; j < 4; j++) acc[mt][nt][j] = 0.f;

    mma_stage<K2, 2>(sm + F_AH, sm + F_AL, sm + F_BH, sm + F_BL,
                     acc, warp_m, warp_n, lane);

#pragma unroll
    for (int mt = 0; mt < 2; mt++) {
        const int r = row0 + warp_m * 32 + mt * 16 + g;
#pragma unroll
        for (int nt = 0; nt < 4; nt++) {
            const int col = warp_n * 32 + nt * 8 + c * 2;
            float2 b = *(const float2*)(bo2 + col);
            if (r < M) {
                float2 o0 = make_float2(acc[mt][nt][0] + b.x, acc[mt][nt][1] + b.y);
                *(float2*)(C + (size_t)r * EMB + col) = o0;
            }
            if (r + 8 < M) {
                float2 o1 = make_float2(acc[mt][nt][2] + b.x, acc[mt][nt][3] + b.y);
                *(float2*)(C + (size_t)(r + 8) * EMB + col) = o1;
            }
        }
    }
}

// ---------------------------------------------------------------------------
// Weight fusion (matrix rows 0..127, bias row 128) + prep
// ---------------------------------------------------------------------------
__global__ void fuse_wb_kernel(const float* __restrict__ Wl2,
                               const float* __restrict__ Wr2,
                               const float* __restrict__ bl2,
                               const float* __restrict__ br2,
                               const float* __restrict__ Wo1,
                               float* __restrict__ Ml, float* __restrict__ Mr,
                               float* __restrict__ cl, float* __restrict__ cr)
{
    const int i = blockIdx.x, j = threadIdx.x;
    const bool rs = (blockIdx.y != 0);
    const int off = rs ? EMB : 0;
    const float* vec = (i < EMB) ? ((rs ? Wr2 : Wl2) + i * EMB) : (rs ? br2 : bl2);
    float s = 0.f;
#pragma unroll 8
    for (int k = 0; k < EMB; k++)
        s += vec[k] * Wo1[(off + k) * EMB + j];
    if (i < EMB) (rs ? Mr : Ml)[i * EMB + j] = s;
    else         (rs ? cr : cl)[j] = s;
}

__global__ void prep_weights_kernel(const float* __restrict__ Wl1,
                                    const float* __restrict__ Wr1,
                                    const float* __restrict__ Ml,
                                    const float* __restrict__ Mr,
                                    const float* __restrict__ Wo2,
                                    __nv_bfloat16* __restrict__ Wl1T,
                                    __nv_bfloat16* __restrict__ Wr1T,
                                    __nv_bfloat16* __restrict__ MlT,
                                    __nv_bfloat16* __restrict__ MrT,
                                    __nv_bfloat16* __restrict__ Wo2T)
{
    const int n = threadIdx.x;
    const float* W; __nv_bfloat16* T; int K;
    switch (blockIdx.x) {
        case 0: W = Wl1; T = Wl1T; K = 64;  break;
        case 1: W = Wr1; T = Wr1T; K = 64;  break;
        case 2: W = Ml;  T = MlT;  K = 128; break;
        case 3: W = Mr;  T = MrT;  K = 128; break;
        default: W = Wo2; T = Wo2T; K = 128; break;
    }
    __nv_bfloat16* Hi = T;
    __nv_bfloat16* Lo = T + EMB * K;
    for (int k = 0; k < K; k++) {
        float w = W[k * EMB + n];
        __nv_bfloat16 h = __float2bfloat16(w);
        __nv_bfloat16 l = __float2bfloat16(w - __bfloat162float(h));
        Hi[n * K + k] = h;
        Lo[n * K + k] = l;
    }
}

// ---------------------------------------------------------------------------
// CSR build: histogram -> block-scan -> offsets -> fill (packed payload)
// ---------------------------------------------------------------------------
__global__ void hist_kernel(const int* __restrict__ eidx, int* __restrict__ cnt, int E) {
    const int e = blockIdx.x * blockDim.x + threadIdx.x;
    if (e < E) atomicAdd(&cnt[eidx[E + e]], 1);
}

__global__ void scan_block_kernel(const int* __restrict__ cnt, int* __restrict__ excl,
                                  int* __restrict__ part, int n) {
    __shared__ int sh[512];
    const int tid = threadIdx.x;
    const int i = blockIdx.x * 512 + tid;
    int v = (i < n) ? cnt[i] : 0;
    int x = v;
    sh[tid] = x;
    __syncthreads();
#pragma unroll
    for (int d = 1; d < 512; d <<= 1) {
        int t = (tid >= d) ? sh[tid - d] : 0;
        __syncthreads();
        x += t;
        sh[tid] = x;
        __syncthreads();
    }
    if (i < n) excl[i] = x - v;
    if (tid == 511) part[blockIdx.x] = x;
}

__global__ void scan_part_kernel(int* __restrict__ part, int* __restrict__ partoff, int nb) {
    __shared__ int sh[1024];
    const int tid = threadIdx.x;
    int v = (tid < nb) ? part[tid] : 0;
    int x = v;
    sh[tid] = x;
    __syncthreads();
#pragma unroll
    for (int d = 1; d < 1024; d <<= 1) {
        int t = (tid >= d) ? sh[tid - d] : 0;
        __syncthreads();
        x += t;
        sh[tid] = x;
        __syncthreads();
    }
    if (tid < nb) partoff[tid] = x - v;
}

__global__ void finalize_rowptr_kernel(const int* __restrict__ excl,
                                       const int* __restrict__ partoff,
                                       int* __restrict__ rowptr,
                                       int* __restrict__ cursor,
                                       int n, int E) {
    const int i = blockIdx.x * 512 + threadIdx.x;
    if (i < n) {
        int r = excl[i] + partoff[blockIdx.x];
        rowptr[i] = r;
        cursor[i] = r;
    }
    if (i == 0) rowptr[n] = E;
}

__global__ void fill_kernel(const int* __restrict__ eidx, const float* __restrict__ ew,
                            int* __restrict__ cursor,
                            int2* __restrict__ epack, int E) {
    const int e = blockIdx.x * blockDim.x + threadIdx.x;
    if (e >= E) return;
    const int src = eidx[e];
    const int dst = eidx[E + e];
    const int pos = atomicAdd(&cursor[dst], 1);
    epack[pos] = make_int2(src, __float_as_int(ew[e]));
}

// ---------------------------------------------------------------------------
// Launch
// ---------------------------------------------------------------------------
extern "C" void kernel_launch(void* const* d_in, const int* in_sizes, int n_in,
                              void* d_out, int out_size)
{
    const float* left  = (const float*)d_in[0];
    const int*   eidx  = (const int*)  d_in[1];
    const float* ew    = (const float*)d_in[2];
    const float* right = (const float*)d_in[3];
    const float* Wl1 = (const float*)d_in[5];
    const float* bl1 = (const float*)d_in[6];
    const float* Wl2 = (const float*)d_in[7];
    const float* bl2 = (const float*)d_in[8];
    const float* Wr1 = (const float*)d_in[9];
    const float* Wr2 = (const float*)d_in[10];
    const float* br2 = (const float*)d_in[11];
    const float* Wo1 = (const float*)d_in[12];
    const float* bo1 = (const float*)d_in[13];
    const float* Wo2 = (const float*)d_in[14];
    const float* bo2 = (const float*)d_in[15];

    const int nL = in_sizes[0] / 64;
    const int E  = in_sizes[1] / 2;
    const int nR = in_sizes[3] / 64;
    const int nO = out_size / EMB;

    float *gL, *gS, *gMl, *gMr, *gcl, *gcr;
    cudaGetSymbolAddress((void**)&gL,  g_L);
    cudaGetSymbolAddress((void**)&gS,  g_S);
    cudaGetSymbolAddress((void**)&gMl, g_Ml);
    cudaGetSymbolAddress((void**)&gMr, g_Mr);
    cudaGetSymbolAddress((void**)&gcl, g_cl);
    cudaGetSymbolAddress((void**)&gcr, g_cr);

    int *gCnt, *gRow, *gExcl, *gPart, *gPoff;
    int2* gEpack;
    cudaGetSymbolAddress((void**)&gCnt,   g_cnt);
    cudaGetSymbolAddress((void**)&gRow,   g_rowptr);
    cudaGetSymbolAddress((void**)&gExcl,  g_excl);
    cudaGetSymbolAddress((void**)&gPart,  g_part);
    cudaGetSymbolAddress((void**)&gPoff,  g_partoff);
    cudaGetSymbolAddress((void**)&gEpack, g_epack);

    __nv_bfloat16 *wl1t, *wr1t, *mlt, *mrt, *wo2t;
    cudaGetSymbolAddress((void**)&wl1t, g_Wl1T);
    cudaGetSymbolAddress((void**)&wr1t, g_Wr1T);
    cudaGetSymbolAddress((void**)&mlt,  g_MlT);
    cudaGetSymbolAddress((void**)&mrt,  g_MrT);
    cudaGetSymbolAddress((void**)&wo2t, g_Wo2T);

    cudaFuncSetAttribute(mlp2_kernel,      cudaFuncAttributeMaxDynamicSharedMemorySize, MLP_SMEM_BYTES);
    cudaFuncSetAttribute(out_fused_kernel, cudaFuncAttributeMaxDynamicSharedMemorySize, F_SMEM_BYTES);

    const int gridL = (nL + 63) / 64;
    const int gridR = (nR + 63) / 64;
    const int gridO = (nO + 63) / 64;
    const int NB = (nR + 511) / 512;

    const uint4* wl1h = (const uint4*)wl1t;
    const uint4* wl1l = (const uint4*)(wl1t + EMB * 64);
    const uint4* wr1h = (const uint4*)wr1t;
    const uint4* wr1l = (const uint4*)(wr1t + EMB * 64);
    const uint4* mlh  = (const uint4*)mlt;
    const uint4* mll  = (const uint4*)(mlt + EMB * EMB);
    const uint4* mrh  = (const uint4*)mrt;
    const uint4* mrl  = (const uint4*)(mrt + EMB * EMB);
    const uint4* wo2h = (const uint4*)wo2t;
    const uint4* wo2l = (const uint4*)(wo2t + EMB * EMB);

    // launch index 0
    fuse_wb_kernel<<<dim3(EMB + 1, 2), EMB>>>(Wl2, Wr2, bl2, br2, Wo1, gMl, gMr, gcl, gcr);
    // launch index 1
    prep_weights_kernel<<<5, EMB>>>(Wl1, Wr1, gMl, gMr, Wo2, wl1t, wr1t, mlt, mrt, wo2t);
    // (memset — not counted by the profiler's launch index)
    cudaMemsetAsync(gCnt, 0, (size_t)nR * sizeof(int));
    // launch index 2
    hist_kernel<<<(E + 255) / 256, 256>>>(eidx, gCnt, E);
    // launch index 3  <- profiler capture target: merged MLP (left + right)
    mlp2_kernel<<<gridL + gridR, 256, MLP_SMEM_BYTES>>>(
        left, right,
        wl1h, wl1l, wr1h, wr1l, bl1,
        mlh, mll, mrh, mrl, gcl, gcr,
        gL, gS, nL, nR, gridL);
    // CSR scan chain
    scan_block_kernel<<<NB, 512>>>(gCnt, gExcl, gPart, nR);
    scan_part_kernel<<<1, 1024>>>(gPart, gPoff, NB);
    finalize_rowptr_kernel<<<NB, 512>>>(gExcl, gPoff, gRow, gCnt, nR, E);
    fill_kernel<<<(E + 255) / 256, 256>>>(eidx, ew, gCnt, gEpack, E);
    // fused gather + output GEMM
    out_fused_kernel<<<gridO, 256, F_SMEM_BYTES>>>(gS, gRow, gEpack, gL,
                                                   wo2h, wo2l, bo1, bo2, (float*)d_out, nO);
}

// round 9
// speedup vs baseline: 1.1233x; 1.0205x over previous
#include <cuda_runtime.h>
#include <cuda_bf16.h>
#include <cstdint>

// Problem constants (fixed by the dataset)
#define N_LEFT   100000
#define N_RIGHT  100000
#define N_EDGES  600000
#define EMB      128

// ---------------------------------------------------------------------------
// Device scratch (allocation-free rule: __device__ globals)
// ---------------------------------------------------------------------------
__device__ float g_L [N_LEFT  * EMB];   // transformed left (scatter source)
__device__ float g_S [N_RIGHT * EMB];   // transformed right + conv accumulator
__device__ float g_Ml[EMB * EMB];       // Wl2 @ Wo1[0:128]
__device__ float g_Mr[EMB * EMB];       // Wr2 @ Wo1[128:256]
__device__ float g_cl[EMB];
__device__ float g_cr[EMB];

// Pre-transposed bf16 hi/lo weight images, [n][k] k-contiguous (B^T layout).
__device__ __align__(16) __nv_bfloat16 g_Wl1T[2][EMB * 64];
__device__ __align__(16) __nv_bfloat16 g_Wr1T[2][EMB * 64];
__device__ __align__(16) __nv_bfloat16 g_MlT [2][EMB * EMB];
__device__ __align__(16) __nv_bfloat16 g_MrT [2][EMB * EMB];
__device__ __align__(16) __nv_bfloat16 g_Wo2T[2][EMB * EMB];

// ---------------------------------------------------------------------------
// PTX helpers (all baseline sm_80+)
// ---------------------------------------------------------------------------
__device__ __forceinline__ void mma16816(float* d, const uint32_t* a, const uint32_t* b) {
    asm volatile(
        "mma.sync.aligned.m16n8k16.row.col.f32.bf16.bf16.f32 "
        "{%0,%1,%2,%3}, {%4,%5,%6,%7}, {%8,%9}, {%0,%1,%2,%3};"
        : "+f"(d[0]), "+f"(d[1]), "+f"(d[2]), "+f"(d[3])
        : "r"(a[0]), "r"(a[1]), "r"(a[2]), "r"(a[3]), "r"(b[0]), "r"(b[1]));
}
__device__ __forceinline__ void ldsm_x4(uint32_t& r0, uint32_t& r1, uint32_t& r2, uint32_t& r3,
                                        uint32_t addr) {
    asm volatile("ldmatrix.sync.aligned.m8n8.x4.shared.b16 {%0,%1,%2,%3}, [%4];"
                 : "=r"(r0), "=r"(r1), "=r"(r2), "=r"(r3) : "r"(addr));
}
__device__ __forceinline__ uint32_t cvta_s(const void* p) {
    return (uint32_t)__cvta_generic_to_shared(p);
}
__device__ __forceinline__ void cp_async16(uint32_t dst, const void* src) {
    asm volatile("cp.async.cg.shared.global [%0], [%1], 16;" :: "r"(dst), "l"(src));
}
__device__ __forceinline__ void cp_commit() {
    asm volatile("cp.async.commit_group;");
}
__device__ __forceinline__ void cp_wait0() {
    asm volatile("cp.async.wait_group 0;");
}

// ---------------------------------------------------------------------------
// MMA stage: acc[MT][4][4] += split3( A[MT*32][K] @ B[128][K]^T )
// smem row stride K+8 (16B-aligned rows, conflict-free ldmatrix).
// ---------------------------------------------------------------------------
template<int K, int MT>
__device__ __forceinline__ void mma_stage(const __nv_bfloat16* __restrict__ Ahi,
                                          const __nv_bfloat16* __restrict__ Alo,
                                          const __nv_bfloat16* __restrict__ Bhi,
                                          const __nv_bfloat16* __restrict__ Blo,
                                          float acc[][4][4],
                                          int warp_m, int warp_n, int lane)
{
    constexpr int SK = K + 8;
    const int tr = lane & 7, quad = lane >> 3;
    const int a_row = warp_m * (MT * 16) + tr + (quad & 1) * 8;
    const int a_col = (quad >> 1) * 8;
    const int b_row = warp_n * 32 + tr + (quad >> 1) * 8;
    const int b_col = (quad & 1) * 8;

    uint32_t aAh = cvta_s(Ahi) + (uint32_t)(a_row * SK + a_col) * 2;
    uint32_t aAl = cvta_s(Alo) + (uint32_t)(a_row * SK + a_col) * 2;
    uint32_t aBh = cvta_s(Bhi) + (uint32_t)(b_row * SK + b_col) * 2;
    uint32_t aBl = cvta_s(Blo) + (uint32_t)(b_row * SK + b_col) * 2;

#pragma unroll
    for (int kc = 0; kc < K / 16; kc++) {
        const uint32_t ko = kc * 32;   // 16 elems = 32 bytes
        uint32_t ah[MT][4], al[MT][4], bh[2][4], bl[2][4];
#pragma unroll
        for (int mt = 0; mt < MT; mt++) {
            const uint32_t mo = (uint32_t)(mt * 16 * SK) * 2 + ko;
            ldsm_x4(ah[mt][0], ah[mt][1], ah[mt][2], ah[mt][3], aAh + mo);
            ldsm_x4(al[mt][0], al[mt][1], al[mt][2], al[mt][3], aAl + mo);
        }
#pragma unroll
        for (int np = 0; np < 2; np++) {
            const uint32_t no = (uint32_t)(np * 16 * SK) * 2 + ko;
            ldsm_x4(bh[np][0], bh[np][1], bh[np][2], bh[np][3], aBh + no);
            ldsm_x4(bl[np][0], bl[np][1], bl[np][2], bl[np][3], aBl + no);
        }
#pragma unroll
        for (int mt = 0; mt < MT; mt++)
#pragma unroll
            for (int nt = 0; nt < 4; nt++) {
                const uint32_t* ph = &bh[nt >> 1][(nt & 1) * 2];
                const uint32_t* pl = &bl[nt >> 1][(nt & 1) * 2];
                mma16816(acc[mt][nt], ah[mt], ph);
                mma16816(acc[mt][nt], ah[mt], pl);
                mma16816(acc[mt][nt], al[mt], ph);
            }
    }
}

// Async copy a [128][K] bf16 image from gmem (packed) into padded smem.
template<int K>
__device__ __forceinline__ void load_B_async(__nv_bfloat16* __restrict__ dst,
                                             const uint4* __restrict__ src, int tid)
{
    constexpr int SK = K + 8;
    constexpr int NV = 128 * K / 8;
#pragma unroll
    for (int i = tid; i < NV; i += 256) {
        const int row = i / (K / 8);
        const int col = (i % (K / 8)) * 8;
        cp_async16(cvta_s(dst + row * SK + col), src + i);
    }
}

// Load A[row0..+63][0..K) fp32 from gmem, optional relu(x + pre_bias),
// bf16 hi/lo split, padded smem. 256 threads, 4 threads/row.
template<int K, bool PRE>
__device__ __forceinline__ void load_A64(__nv_bfloat16* __restrict__ hi,
                                         __nv_bfloat16* __restrict__ lo,
                                         const float* __restrict__ X,
                                         const float* __restrict__ pre_bias,
                                         int row0, int M, int tid)
{
    constexpr int SK = K + 8;
    const int row  = tid >> 2;
    const int grow = row0 + row;
    const bool valid = grow < M;
    const float* xr = X + (size_t)grow * K;
    const int cbase = (tid & 3) * (K / 4);
#pragma unroll
    for (int q = 0; q < K / 16; q++) {
        const int c0 = cbase + q * 4;
        float4 v = valid ? *(const float4*)(xr + c0) : make_float4(0.f, 0.f, 0.f, 0.f);
        if (PRE) {
            float4 pb = *(const float4*)(pre_bias + c0);
            v.x = fmaxf(v.x + pb.x, 0.f);
            v.y = fmaxf(v.y + pb.y, 0.f);
            v.z = fmaxf(v.z + pb.z, 0.f);
            v.w = fmaxf(v.w + pb.w, 0.f);
        }
        __nv_bfloat16 hx = __float2bfloat16(v.x), hy = __float2bfloat16(v.y);
        __nv_bfloat16 hz = __float2bfloat16(v.z), hw = __float2bfloat16(v.w);
        __nv_bfloat16 lx = __float2bfloat16(v.x - __bfloat162float(hx));
        __nv_bfloat16 ly = __float2bfloat16(v.y - __bfloat162float(hy));
        __nv_bfloat16 lz = __float2bfloat16(v.z - __bfloat162float(hz));
        __nv_bfloat16 lw = __float2bfloat16(v.w - __bfloat162float(hw));
        __nv_bfloat162 h0(hx, hy), h1(hz, hw), l0(lx, ly), l1(lz, lw);
        *(uint32_t*)(hi + row * SK + c0)     = *(uint32_t*)&h0;
        *(uint32_t*)(hi + row * SK + c0 + 2) = *(uint32_t*)&h1;
        *(uint32_t*)(lo + row * SK + c0)     = *(uint32_t*)&l0;
        *(uint32_t*)(lo + row * SK + c0 + 2) = *(uint32_t*)&l1;
    }
}

// ---------------------------------------------------------------------------
// MERGED fused 2-layer MLP (left + right in one launch), M=64 per CTA,
// overlaid smem (2 CTAs/SM):  C = relu(X @ W1 [+ b1]) @ W2 + b2
// blockIdx.x < gridL -> left side; else right side.
// ---------------------------------------------------------------------------
#define K1 64
#define K2 128
#define SK1 (K1 + 8)
#define SK2 (K2 + 8)
#define M_B1H 0
#define M_B1L (128 * SK1)                   // 9216
#define M_A1H (2 * 128 * SK1)               // 18432
#define M_A1L (M_A1H + 64 * SK1)            // 23040
#define M_HH  0
#define M_HL  (64 * SK2)                    // 8704
#define M_B2H 18432
#define M_B2L (M_B2H + 128 * SK2)           // 35840
#define MLP_SMEM_ELEMS (M_B2L + 128 * SK2)  // 53248
#define MLP_SMEM_BYTES (MLP_SMEM_ELEMS * 2) // 106496

__global__ void __launch_bounds__(256, 2)
mlp2_kernel(const float* __restrict__ XL, const float* __restrict__ XR,
            const uint4* __restrict__ L_B1hi, const uint4* __restrict__ L_B1lo,
            const uint4* __restrict__ R_B1hi, const uint4* __restrict__ R_B1lo,
            const float* __restrict__ bl1,          // left stage-1 bias (right has none)
            const uint4* __restrict__ L_B2hi, const uint4* __restrict__ L_B2lo,
            const uint4* __restrict__ R_B2hi, const uint4* __restrict__ R_B2lo,
            const float* __restrict__ cl, const float* __restrict__ cr,
            float* __restrict__ CL, float* __restrict__ CR,
            int nL, int nR, int gridL)
{
    extern __shared__ __nv_bfloat16 sm[];
    const int tid = threadIdx.x;
    const int wid = tid >> 5, lane = tid & 31;
    const int warp_m = wid >> 2, warp_n = wid & 3;
    const int g = lane >> 2, c = lane & 3;

    const bool leftSide = (blockIdx.x < gridL);
    const int  bidx  = leftSide ? blockIdx.x : blockIdx.x - gridL;
    const int  row0  = bidx * 64;
    const int  M     = leftSide ? nL : nR;
    const float* X   = leftSide ? XL : XR;
    const uint4* B1hi = leftSide ? L_B1hi : R_B1hi;
    const uint4* B1lo = leftSide ? L_B1lo : R_B1lo;
    const uint4* B2hi = leftSide ? L_B2hi : R_B2hi;
    const uint4* B2lo = leftSide ? L_B2lo : R_B2lo;
    const float* bias1 = leftSide ? bl1 : nullptr;
    const float* bias2 = leftSide ? cl : cr;
    float* C          = leftSide ? CL : CR;

    load_B_async<K1>(sm + M_B1H, B1hi, tid);
    load_B_async<K1>(sm + M_B1L, B1lo, tid);
    cp_commit();
    load_A64<K1, false>(sm + M_A1H, sm + M_A1L, X, nullptr, row0, M, tid);  // overlaps B1
    cp_wait0();
    __syncthreads();

    float acc[2][4][4];
#pragma unroll
    for (int mt = 0; mt < 2; mt++)
#pragma unroll
        for (int nt = 0; nt < 4; nt++)
#pragma unroll
            for (int j = 0; j < 4; j++) acc[mt][nt][j] = 0.f;

    mma_stage<K1, 2>(sm + M_A1H, sm + M_A1L, sm + M_B1H, sm + M_B1L,
                     acc, warp_m, warp_n, lane);
    __syncthreads();   // all warps done reading A1/B1

    // prefetch B2 over A1/X region (A1 fully consumed), overlapping epilogue-1
    load_B_async<K2>(sm + M_B2H, B2hi, tid);
    load_B_async<K2>(sm + M_B2L, B2lo, tid);
    cp_commit();

    // epilogue 1: H = relu(acc + b1) -> bf16 hi/lo over B1 region
#pragma unroll
    for (int mt = 0; mt < 2; mt++) {
        const int row = warp_m * 32 + mt * 16 + g;
#pragma unroll
        for (int nt = 0; nt < 4; nt++) {
            const int col = warp_n * 32 + nt * 8 + c * 2;
            float v0 = acc[mt][nt][0], v1 = acc[mt][nt][1];
            float v2 = acc[mt][nt][2], v3 = acc[mt][nt][3];
            if (bias1) {
                float2 b = *(const float2*)(bias1 + col);
                v0 += b.x; v1 += b.y; v2 += b.x; v3 += b.y;
            }
            v0 = fmaxf(v0, 0.f); v1 = fmaxf(v1, 0.f);
            v2 = fmaxf(v2, 0.f); v3 = fmaxf(v3, 0.f);
            __nv_bfloat16 h0 = __float2bfloat16(v0), h1 = __float2bfloat16(v1);
            __nv_bfloat16 h2 = __float2bfloat16(v2), h3 = __float2bfloat16(v3);
            __nv_bfloat162 hp0(h0, h1), hp1(h2, h3);
            __nv_bfloat162 lp0(__float2bfloat16(v0 - __bfloat162float(h0)),
                               __float2bfloat16(v1 - __bfloat162float(h1)));
            __nv_bfloat162 lp1(__float2bfloat16(v2 - __bfloat162float(h2)),
                               __float2bfloat16(v3 - __bfloat162float(h3)));
            *(uint32_t*)(sm + M_HH + row * SK2 + col)       = *(uint32_t*)&hp0;
            *(uint32_t*)(sm + M_HH + (row + 8) * SK2 + col) = *(uint32_t*)&hp1;
            *(uint32_t*)(sm + M_HL + row * SK2 + col)       = *(uint32_t*)&lp0;
            *(uint32_t*)(sm + M_HL + (row + 8) * SK2 + col) = *(uint32_t*)&lp1;
        }
    }
    cp_wait0();
    __syncthreads();

#pragma unroll
    for (int mt = 0; mt < 2; mt++)
#pragma unroll
        for (int nt = 0; nt < 4; nt++)
#pragma unroll
            for (int j = 0; j < 4; j++) acc[mt][nt][j] = 0.f;

    mma_stage<K2, 2>(sm + M_HH, sm + M_HL, sm + M_B2H, sm + M_B2L,
                     acc, warp_m, warp_n, lane);

#pragma unroll
    for (int mt = 0; mt < 2; mt++) {
        const int r = row0 + warp_m * 32 + mt * 16 + g;
#pragma unroll
        for (int nt = 0; nt < 4; nt++) {
            const int col = warp_n * 32 + nt * 8 + c * 2;
            float2 b = *(const float2*)(bias2 + col);
            if (r < M) {
                float2 o0 = make_float2(acc[mt][nt][0] + b.x, acc[mt][nt][1] + b.y);
                *(float2*)(C + (size_t)r * EMB + col) = o0;
            }
            if (r + 8 < M) {
                float2 o1 = make_float2(acc[mt][nt][2] + b.x, acc[mt][nt][3] + b.y);
                *(float2*)(C + (size_t)(r + 8) * EMB + col) = o1;
            }
        }
    }
}

// ---------------------------------------------------------------------------
// Edge scatter: one warp per edge.  S[dst] += w_e * L[src]  (red.global.v4)
// ---------------------------------------------------------------------------
__global__ void scatter_kernel(const int* __restrict__ eidx,
                               const float* __restrict__ ew,
                               const float* __restrict__ L,
                               float* __restrict__ S,
                               int E)
{
    const int warp = (blockIdx.x * blockDim.x + threadIdx.x) >> 5;
    const int lane = threadIdx.x & 31;
    if (warp >= E) return;

    const int src = eidx[warp];
    const int dst = eidx[E + warp];
    const float w = ew[warp];

    float4 v = *(const float4*)(L + (size_t)src * EMB + lane * 4);
    float* out = S + (size_t)dst * EMB + lane * 4;
    asm volatile("red.global.add.v4.f32 [%0], {%1, %2, %3, %4};"
                 :: "l"(out), "f"(w * v.x), "f"(w * v.y), "f"(w * v.z), "f"(w * v.w)
                 : "memory");
}

// ---------------------------------------------------------------------------
// Output GEMM, M=64 per CTA (2 CTAs/SM):
//   out = relu(S + bo1) @ Wo2 + bo2
// ---------------------------------------------------------------------------
#define F_AH 0
#define F_AL (64 * SK2)                  // 8704
#define F_BH (2 * 64 * SK2)              // 17408
#define F_BL (F_BH + 128 * SK2)          // 34816
#define F_SMEM_ELEMS (F_BL + 128 * SK2)  // 52224
#define F_SMEM_BYTES (F_SMEM_ELEMS * 2)  // 104448

__global__ void __launch_bounds__(256, 2)
out_gemm_kernel(const float* __restrict__ S,
                const uint4* __restrict__ Bhi, const uint4* __restrict__ Blo,
                const float* __restrict__ bo1,
                const float* __restrict__ bo2,
                float* __restrict__ C, int M)
{
    extern __shared__ __nv_bfloat16 sm[];
    const int tid = threadIdx.x;
    const int wid = tid >> 5, lane = tid & 31;
    const int warp_m = wid >> 2, warp_n = wid & 3;
    const int g = lane >> 2, c = lane & 3;
    const int row0 = blockIdx.x * 64;

    load_B_async<K2>(sm + F_BH, Bhi, tid);
    load_B_async<K2>(sm + F_BL, Blo, tid);
    cp_commit();
    load_A64<K2, true>(sm + F_AH, sm + F_AL, S, bo1, row0, M, tid);   // overlaps B fetch
    cp_wait0();
    __syncthreads();

    float acc[2][4][4];
#pragma unroll
    for (int mt = 0; mt < 2; mt++)
#pragma unroll
        for (int nt = 0; nt < 4; nt++)
#pragma unroll
            for (int j = 0; j < 4; j++) acc[mt][nt][j] = 0.f;

    mma_stage<K2, 2>(sm + F_AH, sm + F_AL, sm + F_BH, sm + F_BL,
                     acc, warp_m, warp_n, lane);

#pragma unroll
    for (int mt = 0; mt < 2; mt++) {
        const int r = row0 + warp_m * 32 + mt * 16 + g;
#pragma unroll
        for (int nt = 0; nt < 4; nt++) {
            const int col = warp_n * 32 + nt * 8 + c * 2;
            float2 b = *(const float2*)(bo2 + col);
            if (r < M) {
                float2 o0 = make_float2(acc[mt][nt][0] + b.x, acc[mt][nt][1] + b.y);
                *(float2*)(C + (size_t)r * EMB + col) = o0;
            }
            if (r + 8 < M) {
                float2 o1 = make_float2(acc[mt][nt][2] + b.x, acc[mt][nt][3] + b.y);
                *(float2*)(C + (size_t)(r + 8) * EMB + col) = o1;
            }
        }
    }
}

// ---------------------------------------------------------------------------
// Weight fusion (matrix rows 0..127, bias row 128) + prep
// ---------------------------------------------------------------------------
__global__ void fuse_wb_kernel(const float* __restrict__ Wl2,
                               const float* __restrict__ Wr2,
                               const float* __restrict__ bl2,
                               const float* __restrict__ br2,
                               const float* __restrict__ Wo1,
                               float* __restrict__ Ml, float* __restrict__ Mr,
                               float* __restrict__ cl, float* __restrict__ cr)
{
    const int i = blockIdx.x, j = threadIdx.x;
    const bool rs = (blockIdx.y != 0);
    const int off = rs ? EMB : 0;
    const float* vec = (i < EMB) ? ((rs ? Wr2 : Wl2) + i * EMB) : (rs ? br2 : bl2);
    float s = 0.f;
#pragma unroll 8
    for (int k = 0; k < EMB; k++)
        s += vec[k] * Wo1[(off + k) * EMB + j];
    if (i < EMB) (rs ? Mr : Ml)[i * EMB + j] = s;
    else         (rs ? cr : cl)[j] = s;
}

__global__ void prep_weights_kernel(const float* __restrict__ Wl1,
                                    const float* __restrict__ Wr1,
                                    const float* __restrict__ Ml,
                                    const float* __restrict__ Mr,
                                    const float* __restrict__ Wo2,
                                    __nv_bfloat16* __restrict__ Wl1T,
                                    __nv_bfloat16* __restrict__ Wr1T,
                                    __nv_bfloat16* __restrict__ MlT,
                                    __nv_bfloat16* __restrict__ MrT,
                                    __nv_bfloat16* __restrict__ Wo2T)
{
    const int n = threadIdx.x;
    const float* W; __nv_bfloat16* T; int K;
    switch (blockIdx.x) {
        case 0: W = Wl1; T = Wl1T; K = 64;  break;
        case 1: W = Wr1; T = Wr1T; K = 64;  break;
        case 2: W = Ml;  T = MlT;  K = 128; break;
        case 3: W = Mr;  T = MrT;  K = 128; break;
        default: W = Wo2; T = Wo2T; K = 128; break;
    }
    __nv_bfloat16* Hi = T;
    __nv_bfloat16* Lo = T + EMB * K;
    for (int k = 0; k < K; k++) {
        float w = W[k * EMB + n];
        __nv_bfloat16 h = __float2bfloat16(w);
        __nv_bfloat16 l = __float2bfloat16(w - __bfloat162float(h));
        Hi[n * K + k] = h;
        Lo[n * K + k] = l;
    }
}

// ---------------------------------------------------------------------------
// Launch
// ---------------------------------------------------------------------------
extern "C" void kernel_launch(void* const* d_in, const int* in_sizes, int n_in,
                              void* d_out, int out_size)
{
    const float* left  = (const float*)d_in[0];
    const int*   eidx  = (const int*)  d_in[1];
    const float* ew    = (const float*)d_in[2];
    const float* right = (const float*)d_in[3];
    const float* Wl1 = (const float*)d_in[5];
    const float* bl1 = (const float*)d_in[6];
    const float* Wl2 = (const float*)d_in[7];
    const float* bl2 = (const float*)d_in[8];
    const float* Wr1 = (const float*)d_in[9];
    const float* Wr2 = (const float*)d_in[10];
    const float* br2 = (const float*)d_in[11];
    const float* Wo1 = (const float*)d_in[12];
    const float* bo1 = (const float*)d_in[13];
    const float* Wo2 = (const float*)d_in[14];
    const float* bo2 = (const float*)d_in[15];

    const int nL = in_sizes[0] / 64;
    const int E  = in_sizes[1] / 2;
    const int nR = in_sizes[3] / 64;
    const int nO = out_size / EMB;

    float *gL, *gS, *gMl, *gMr, *gcl, *gcr;
    cudaGetSymbolAddress((void**)&gL,  g_L);
    cudaGetSymbolAddress((void**)&gS,  g_S);
    cudaGetSymbolAddress((void**)&gMl, g_Ml);
    cudaGetSymbolAddress((void**)&gMr, g_Mr);
    cudaGetSymbolAddress((void**)&gcl, g_cl);
    cudaGetSymbolAddress((void**)&gcr, g_cr);

    __nv_bfloat16 *wl1t, *wr1t, *mlt, *mrt, *wo2t;
    cudaGetSymbolAddress((void**)&wl1t, g_Wl1T);
    cudaGetSymbolAddress((void**)&wr1t, g_Wr1T);
    cudaGetSymbolAddress((void**)&mlt,  g_MlT);
    cudaGetSymbolAddress((void**)&mrt,  g_MrT);
    cudaGetSymbolAddress((void**)&wo2t, g_Wo2T);

    cudaFuncSetAttribute(mlp2_kernel,     cudaFuncAttributeMaxDynamicSharedMemorySize, MLP_SMEM_BYTES);
    cudaFuncSetAttribute(out_gemm_kernel, cudaFuncAttributeMaxDynamicSharedMemorySize, F_SMEM_BYTES);

    const int gridL = (nL + 63) / 64;
    const int gridR = (nR + 63) / 64;
    const int gridO = (nO + 63) / 64;

    const uint4* wl1h = (const uint4*)wl1t;
    const uint4* wl1l = (const uint4*)(wl1t + EMB * 64);
    const uint4* wr1h = (const uint4*)wr1t;
    const uint4* wr1l = (const uint4*)(wr1t + EMB * 64);
    const uint4* mlh  = (const uint4*)mlt;
    const uint4* mll  = (const uint4*)(mlt + EMB * EMB);
    const uint4* mrh  = (const uint4*)mrt;
    const uint4* mrl  = (const uint4*)(mrt + EMB * EMB);
    const uint4* wo2h = (const uint4*)wo2t;
    const uint4* wo2l = (const uint4*)(wo2t + EMB * EMB);

    // 1) fold Wl2@Wo1a / Wr2@Wo1b (+ bias rows), then transpose+split to bf16
    fuse_wb_kernel<<<dim3(EMB + 1, 2), EMB>>>(Wl2, Wr2, bl2, br2, Wo1, gMl, gMr, gcl, gcr);
    prep_weights_kernel<<<5, EMB>>>(Wl1, Wr1, gMl, gMr, Wo2, wl1t, wr1t, mlt, mrt, wo2t);
    // 2) merged MLP: L = relu(left@Wl1+bl1)@Ml+cl ; S = relu(right@Wr1)@Mr+cr
    mlp2_kernel<<<gridL + gridR, 256, MLP_SMEM_BYTES>>>(
        left, right,
        wl1h, wl1l, wr1h, wr1l, bl1,
        mlh, mll, mrh, mrl, gcl, gcr,
        gL, gS, nL, nR, gridL);
    // 3) S[dst] += e * L[src]   (edge-parallel vector reductions)
    scatter_kernel<<<(E + 7) / 8, 256>>>(eidx, ew, gL, gS, E);
    // 4) out = relu(S + bo1) @ Wo2 + bo2
    out_gemm_kernel<<<gridO, 256, F_SMEM_BYTES>>>(gS, wo2h, wo2l, bo1, bo2, (float*)d_out, nO);
}